// round 2
// baseline (speedup 1.0000x reference)
#include <cuda_runtime.h>
#include <cstddef>

// ---------------------------------------------------------------------------
// Problem constants
// ---------------------------------------------------------------------------
#define B_   32
#define S_   512
#define D_   512
#define H_   8
#define L_   4
#define F_   2048
#define DK_  64
#define MROWS (B_ * S_)            // 16384 token rows

// ---------------------------------------------------------------------------
// Scratch (static device arrays: no allocations allowed)
// ---------------------------------------------------------------------------
__device__ float g_x  [MROWS * D_];   // running activations x
__device__ float g_y  [MROWS * D_];   // y = qa + pos (constant across layers)
__device__ float g_kq [MROWS * D_];   // kq projection
__device__ float g_v  [MROWS * D_];   // v projection
__device__ float g_ctx[MROWS * D_];   // attention context
__device__ float g_o  [MROWS * D_];   // gemm outputs pre-LN
__device__ float g_h  [MROWS * F_];   // FFN hidden

// ---------------------------------------------------------------------------
// x = q + pe ; y = qa + pe   (pe broadcast over batch)
// ---------------------------------------------------------------------------
__global__ void add_pos_kernel(const float4* __restrict__ q,
                               const float4* __restrict__ qa,
                               const float4* __restrict__ pe,
                               float4* __restrict__ x,
                               float4* __restrict__ y)
{
    int i = blockIdx.x * blockDim.x + threadIdx.x;   // over MROWS*D_/4
    if (i >= MROWS * D_ / 4) return;
    int pi = i % (S_ * D_ / 4);
    float4 p = pe[pi];
    float4 a = q[i];
    a.x += p.x; a.y += p.y; a.z += p.z; a.w += p.w;
    x[i] = a;
    float4 b = qa[i];
    b.x += p.x; b.y += p.y; b.z += p.z; b.w += p.w;
    y[i] = b;
}

// ---------------------------------------------------------------------------
// SGEMM: C[M,N] = A[M,K] @ W[N,K]^T + bias[N]  (optional ReLU)
// BM=BN=128, BK=16, 256 threads, 8x8 microtile per thread.
// Register-prefetch software pipeline: next k-stage LDGs are issued before
// computing the current stage, hiding gmem latency behind 1024 FMAs/thread.
// M,N,K all multiples of the tile sizes here -> no bounds checks.
// ---------------------------------------------------------------------------
template <bool RELU>
__global__ void __launch_bounds__(256)
gemm_kernel(const float* __restrict__ A,
            const float* __restrict__ W,
            const float* __restrict__ bias,
            float* __restrict__ C,
            int M, int N, int K)
{
    __shared__ float As[16][128];
    __shared__ float Bs[16][128];

    const int tid = threadIdx.x;
    const int ty  = tid >> 4;      // 0..15  -> 8 output rows each
    const int tx  = tid & 15;      // 0..15  -> 8 output cols each
    const int row0 = blockIdx.y * 128;
    const int col0 = blockIdx.x * 128;

    const float* Aptr = A + (size_t)row0 * K;
    const float* Wptr = W + (size_t)col0 * K;

    // each thread owns 2 (row, c4) slots per matrix per stage
    const int r0_  = tid >> 2;               // 0..63
    const int r1_  = r0_ + 64;               // 64..127
    const int c4_  = (tid & 3) << 2;         // 0,4,8,12

    float acc[8][8];
#pragma unroll
    for (int i = 0; i < 8; i++)
#pragma unroll
        for (int j = 0; j < 8; j++) acc[i][j] = 0.0f;

    // prefetch stage 0 into registers
    float4 pa0 = *(const float4*)(Aptr + (size_t)r0_ * K + c4_);
    float4 pa1 = *(const float4*)(Aptr + (size_t)r1_ * K + c4_);
    float4 pb0 = *(const float4*)(Wptr + (size_t)r0_ * K + c4_);
    float4 pb1 = *(const float4*)(Wptr + (size_t)r1_ * K + c4_);

    for (int k0 = 0; k0 < K; k0 += 16) {
        // stage registers -> smem (transposed [k][m] layout)
        As[c4_ + 0][r0_] = pa0.x; As[c4_ + 1][r0_] = pa0.y;
        As[c4_ + 2][r0_] = pa0.z; As[c4_ + 3][r0_] = pa0.w;
        As[c4_ + 0][r1_] = pa1.x; As[c4_ + 1][r1_] = pa1.y;
        As[c4_ + 2][r1_] = pa1.z; As[c4_ + 3][r1_] = pa1.w;
        Bs[c4_ + 0][r0_] = pb0.x; Bs[c4_ + 1][r0_] = pb0.y;
        Bs[c4_ + 2][r0_] = pb0.z; Bs[c4_ + 3][r0_] = pb0.w;
        Bs[c4_ + 0][r1_] = pb1.x; Bs[c4_ + 1][r1_] = pb1.y;
        Bs[c4_ + 2][r1_] = pb1.z; Bs[c4_ + 3][r1_] = pb1.w;
        __syncthreads();

        // prefetch next stage while computing this one
        const int kn = k0 + 16;
        if (kn < K) {
            pa0 = *(const float4*)(Aptr + (size_t)r0_ * K + kn + c4_);
            pa1 = *(const float4*)(Aptr + (size_t)r1_ * K + kn + c4_);
            pb0 = *(const float4*)(Wptr + (size_t)r0_ * K + kn + c4_);
            pb1 = *(const float4*)(Wptr + (size_t)r1_ * K + kn + c4_);
        }

#pragma unroll
        for (int kk = 0; kk < 16; kk++) {
            float a[8], b[8];
            *(float4*)&a[0] = *(const float4*)&As[kk][ty * 8];
            *(float4*)&a[4] = *(const float4*)&As[kk][ty * 8 + 4];
            *(float4*)&b[0] = *(const float4*)&Bs[kk][tx * 8];
            *(float4*)&b[4] = *(const float4*)&Bs[kk][tx * 8 + 4];
#pragma unroll
            for (int i = 0; i < 8; i++)
#pragma unroll
                for (int j = 0; j < 8; j++)
                    acc[i][j] += a[i] * b[j];
        }
        __syncthreads();   // all reads done before next stage overwrites smem
    }

    // epilogue: bias (+ReLU), vectorized stores
#pragma unroll
    for (int i = 0; i < 8; i++) {
        int r = row0 + ty * 8 + i;
#pragma unroll
        for (int j = 0; j < 8; j += 4) {
            int c = col0 + tx * 8 + j;
            float4 o;
            o.x = acc[i][j + 0] + bias[c + 0];
            o.y = acc[i][j + 1] + bias[c + 1];
            o.z = acc[i][j + 2] + bias[c + 2];
            o.w = acc[i][j + 3] + bias[c + 3];
            if (RELU) {
                o.x = fmaxf(o.x, 0.0f); o.y = fmaxf(o.y, 0.0f);
                o.z = fmaxf(o.z, 0.0f); o.w = fmaxf(o.w, 0.0f);
            }
            *(float4*)&C[(size_t)r * N + c] = o;
        }
    }
}

// ---------------------------------------------------------------------------
// Fused causal attention (flash-style, online softmax).
// scores[s,t] = (kq_s . kq_t) * scale * fr[b,s]; allowed iff t < s (strict).
// Query row s==0 produces zero context (matches attn.at[:,:,0,:].set(0)).
// Block: 256 threads handles one (b, h, 64-query tile). Tiles of 64 keys.
// smem: Qs[64][64], KPs[64][65] (K tile, then reused for P), Vs[64][64].
// ---------------------------------------------------------------------------
#define ATTN_SMEM ((64 * 64 + 64 * 65 + 64 * 64) * 4)   // 49408 bytes

__global__ void __launch_bounds__(256)
attn_kernel(const float* __restrict__ kq,
            const float* __restrict__ v,
            const float* __restrict__ fr,
            float* __restrict__ ctx)
{
    extern __shared__ float sm[];
    float* Qs  = sm;                       // [64][64]
    float* KPs = sm + 64 * 64;             // [64][65] padded
    float* Vs  = sm + 64 * 64 + 64 * 65;   // [64][64]

    const int qt = blockIdx.x;     // query tile 0..7
    const int h  = blockIdx.y;
    const int b  = blockIdx.z;
    const int tid = threadIdx.x;
    const int ty = tid >> 4;       // 0..15 -> 4 query rows each
    const int tx = tid & 15;       // 0..15 -> 4 key cols / 4 dk cols each
    const int s0 = qt * 64;

    // load Q tile (rows s0..s0+63, dims h*64..h*64+63)
#pragma unroll
    for (int it = 0; it < 4; it++) {
        int i  = tid + it * 256;           // 0..1023 float4 slots
        int r  = i >> 4;
        int c4 = (i & 15) << 2;
        float4 qv = *(const float4*)&kq[((size_t)(b * S_ + s0 + r)) * D_ + h * DK_ + c4];
        Qs[r * 64 + c4 + 0] = qv.x; Qs[r * 64 + c4 + 1] = qv.y;
        Qs[r * 64 + c4 + 2] = qv.z; Qs[r * 64 + c4 + 3] = qv.w;
    }

    float m_i[4], l_i[4], acc[4][4];
#pragma unroll
    for (int i = 0; i < 4; i++) {
        m_i[i] = -1e30f; l_i[i] = 0.0f;
#pragma unroll
        for (int j = 0; j < 4; j++) acc[i][j] = 0.0f;
    }

    float rowf[4];   // scale * forget_rate per query row
#pragma unroll
    for (int i = 0; i < 4; i++)
        rowf[i] = 0.125f * fr[b * S_ + s0 + ty * 4 + i];

    for (int kt = 0; kt <= qt; kt++) {
        __syncthreads();   // prior P/V reads done before overwriting buffers
        const int t0 = kt * 64;
#pragma unroll
        for (int it = 0; it < 4; it++) {
            int i  = tid + it * 256;
            int r  = i >> 4;
            int c4 = (i & 15) << 2;
            size_t base = ((size_t)(b * S_ + t0 + r)) * D_ + h * DK_ + c4;
            float4 kk = *(const float4*)&kq[base];
            KPs[r * 65 + c4 + 0] = kk.x; KPs[r * 65 + c4 + 1] = kk.y;
            KPs[r * 65 + c4 + 2] = kk.z; KPs[r * 65 + c4 + 3] = kk.w;
            float4 vv = *(const float4*)&v[base];
            Vs[r * 64 + c4 + 0] = vv.x; Vs[r * 64 + c4 + 1] = vv.y;
            Vs[r * 64 + c4 + 2] = vv.z; Vs[r * 64 + c4 + 3] = vv.w;
        }
        __syncthreads();

        // S = Q @ K^T  (4x4 per thread)
        float sc[4][4];
#pragma unroll
        for (int i = 0; i < 4; i++)
#pragma unroll
            for (int j = 0; j < 4; j++) sc[i][j] = 0.0f;

#pragma unroll 8
        for (int k = 0; k < 64; k++) {
            float qreg[4], kreg[4];
#pragma unroll
            for (int i = 0; i < 4; i++) qreg[i] = Qs[(ty * 4 + i) * 64 + k];
#pragma unroll
            for (int j = 0; j < 4; j++) kreg[j] = KPs[(tx * 4 + j) * 65 + k];
#pragma unroll
            for (int i = 0; i < 4; i++)
#pragma unroll
                for (int j = 0; j < 4; j++)
                    sc[i][j] += qreg[i] * kreg[j];
        }

        // scale*fr then strict-causal mask (diagonal tile only; kt<qt fully allowed)
        const bool diag = (kt == qt);
#pragma unroll
        for (int i = 0; i < 4; i++)
#pragma unroll
            for (int j = 0; j < 4; j++) {
                sc[i][j] *= rowf[i];
                if (diag && (tx * 4 + j >= ty * 4 + i)) sc[i][j] = -1e30f;
            }

        // row max across the 16-thread tx group
        float mt[4];
#pragma unroll
        for (int i = 0; i < 4; i++)
            mt[i] = fmaxf(fmaxf(sc[i][0], sc[i][1]), fmaxf(sc[i][2], sc[i][3]));
#pragma unroll
        for (int off = 8; off >= 1; off >>= 1)
#pragma unroll
            for (int i = 0; i < 4; i++)
                mt[i] = fmaxf(mt[i], __shfl_xor_sync(0xffffffffu, mt[i], off));

        float p[4][4], rs[4];
#pragma unroll
        for (int i = 0; i < 4; i++) {
            float mnew  = fmaxf(m_i[i], mt[i]);
            float alpha = __expf(m_i[i] - mnew);
            m_i[i] = mnew;
            rs[i]  = 0.0f;
#pragma unroll
            for (int j = 0; j < 4; j++) {
                p[i][j] = __expf(sc[i][j] - mnew);
                rs[i]  += p[i][j];
            }
            l_i[i] *= alpha;
#pragma unroll
            for (int j = 0; j < 4; j++) acc[i][j] *= alpha;
        }
#pragma unroll
        for (int off = 8; off >= 1; off >>= 1)
#pragma unroll
            for (int i = 0; i < 4; i++)
                rs[i] += __shfl_xor_sync(0xffffffffu, rs[i], off);
#pragma unroll
        for (int i = 0; i < 4; i++) l_i[i] += rs[i];

        // stage P into the K buffer, then O += P @ V
        __syncthreads();
#pragma unroll
        for (int i = 0; i < 4; i++)
#pragma unroll
            for (int j = 0; j < 4; j++)
                KPs[(ty * 4 + i) * 65 + tx * 4 + j] = p[i][j];
        __syncthreads();

#pragma unroll 8
        for (int k = 0; k < 64; k++) {
            float pr[4], vr[4];
#pragma unroll
            for (int i = 0; i < 4; i++) pr[i] = KPs[(ty * 4 + i) * 65 + k];
#pragma unroll
            for (int j = 0; j < 4; j++) vr[j] = Vs[k * 64 + tx * 4 + j];
#pragma unroll
            for (int i = 0; i < 4; i++)
#pragma unroll
                for (int j = 0; j < 4; j++)
                    acc[i][j] += pr[i] * vr[j];
        }
    }

    // write ctx (row s==0 forced to zero, matching the reference)
#pragma unroll
    for (int i = 0; i < 4; i++) {
        int srow  = s0 + ty * 4 + i;
        float inv = 1.0f / l_i[i];
        float4 o;
        o.x = acc[i][0] * inv; o.y = acc[i][1] * inv;
        o.z = acc[i][2] * inv; o.w = acc[i][3] * inv;
        if (srow == 0) { o.x = 0.0f; o.y = 0.0f; o.z = 0.0f; o.w = 0.0f; }
        *(float4*)&ctx[((size_t)(b * S_ + srow)) * D_ + h * DK_ + tx * 4] = o;
    }
}

// ---------------------------------------------------------------------------
// xout = LayerNorm(xin + res) * g + beta   (row = one token, D=512)
// 128 threads per row, float4 per thread.
// ---------------------------------------------------------------------------
__global__ void __launch_bounds__(128)
add_ln_kernel(const float* __restrict__ xin,
              const float* __restrict__ res,
              const float* __restrict__ g,
              const float* __restrict__ beta,
              float* __restrict__ xout)
{
    const int row = blockIdx.x;
    const int tid = threadIdx.x;

    float4 a = ((const float4*)(xin + (size_t)row * D_))[tid];
    float4 b = ((const float4*)(res + (size_t)row * D_))[tid];
    float v0 = a.x + b.x, v1 = a.y + b.y, v2 = a.z + b.z, v3 = a.w + b.w;

    float s  = v0 + v1 + v2 + v3;
    float sq = v0 * v0 + v1 * v1 + v2 * v2 + v3 * v3;
#pragma unroll
    for (int off = 16; off >= 1; off >>= 1) {
        s  += __shfl_xor_sync(0xffffffffu, s,  off);
        sq += __shfl_xor_sync(0xffffffffu, sq, off);
    }
    __shared__ float ss[4], ssq[4];
    int w = tid >> 5, lane = tid & 31;
    if (lane == 0) { ss[w] = s; ssq[w] = sq; }
    __syncthreads();
    s  = ss[0]  + ss[1]  + ss[2]  + ss[3];
    sq = ssq[0] + ssq[1] + ssq[2] + ssq[3];

    const float mu   = s * (1.0f / (float)D_);
    const float var  = sq * (1.0f / (float)D_) - mu * mu;
    const float rstd = rsqrtf(var + 1e-5f);

    float4 gg = ((const float4*)g)[tid];
    float4 bb = ((const float4*)beta)[tid];
    float4 o;
    o.x = (v0 - mu) * rstd * gg.x + bb.x;
    o.y = (v1 - mu) * rstd * gg.y + bb.y;
    o.z = (v2 - mu) * rstd * gg.z + bb.z;
    o.w = (v3 - mu) * rstd * gg.w + bb.w;
    ((float4*)(xout + (size_t)row * D_))[tid] = o;
}

// ---------------------------------------------------------------------------
// Orchestration
// ---------------------------------------------------------------------------
extern "C" void kernel_launch(void* const* d_in, const int* in_sizes, int n_in,
                              void* d_out, int out_size)
{
    const float* q   = (const float*)d_in[0];
    const float* qa  = (const float*)d_in[1];
    const float* fr  = (const float*)d_in[2];
    const float* pe  = (const float*)d_in[3];
    const float* Wk  = (const float*)d_in[4];
    const float* bk  = (const float*)d_in[5];
    const float* Wv  = (const float*)d_in[6];
    const float* bv  = (const float*)d_in[7];
    const float* Wo  = (const float*)d_in[8];
    const float* bo  = (const float*)d_in[9];
    const float* W1  = (const float*)d_in[10];
    const float* b1  = (const float*)d_in[11];
    const float* W2  = (const float*)d_in[12];
    const float* b2  = (const float*)d_in[13];
    const float* g1  = (const float*)d_in[14];
    const float* be1 = (const float*)d_in[15];
    const float* g2  = (const float*)d_in[16];
    const float* be2 = (const float*)d_in[17];
    float* out = (float*)d_out;

    float *x, *y, *kqb, *vb, *ctxb, *ob, *hb;
    cudaGetSymbolAddress((void**)&x,    g_x);
    cudaGetSymbolAddress((void**)&y,    g_y);
    cudaGetSymbolAddress((void**)&kqb,  g_kq);
    cudaGetSymbolAddress((void**)&vb,   g_v);
    cudaGetSymbolAddress((void**)&ctxb, g_ctx);
    cudaGetSymbolAddress((void**)&ob,   g_o);
    cudaGetSymbolAddress((void**)&hb,   g_h);

    cudaFuncSetAttribute(attn_kernel,
                         cudaFuncAttributeMaxDynamicSharedMemorySize, ATTN_SMEM);

    {
        int n4 = MROWS * D_ / 4;
        add_pos_kernel<<<(n4 + 255) / 256, 256>>>(
            (const float4*)q, (const float4*)qa, (const float4*)pe,
            (float4*)x, (float4*)y);
    }

    const dim3 gD(D_ / 128, MROWS / 128);   // (4, 128)
    const dim3 gF(F_ / 128, MROWS / 128);   // (16, 128)
    const dim3 gA(S_ / 64, H_, B_);         // (8, 8, 32)

    for (int l = 0; l < L_; l++) {
        const size_t wDD = (size_t)l * D_ * D_;
        const size_t wFD = (size_t)l * F_ * D_;

        gemm_kernel<false><<<gD, 256>>>(x, Wk + wDD, bk + l * D_, kqb, MROWS, D_, D_);
        gemm_kernel<false><<<gD, 256>>>(y, Wv + wDD, bv + l * D_, vb,  MROWS, D_, D_);
        attn_kernel<<<gA, 256, ATTN_SMEM>>>(kqb, vb, fr, ctxb);
        gemm_kernel<false><<<gD, 256>>>(ctxb, Wo + wDD, bo + l * D_, ob, MROWS, D_, D_);
        add_ln_kernel<<<MROWS, 128>>>(x, ob, g1 + l * D_, be1 + l * D_, x);
        gemm_kernel<true ><<<gF, 256>>>(x, W1 + wFD, b1 + l * F_, hb, MROWS, F_, D_);
        gemm_kernel<false><<<gD, 256>>>(hb, W2 + wFD, b2 + l * D_, ob, MROWS, D_, F_);
        add_ln_kernel<<<MROWS, 128>>>(x, ob, g2 + l * D_, be2 + l * D_,
                                      (l == L_ - 1) ? out : x);
    }
}

// round 5
// speedup vs baseline: 1.5204x; 1.5204x over previous
#include <cuda_runtime.h>
#include <cstdint>
#include <cstddef>

// ---------------------------------------------------------------------------
// Problem constants
// ---------------------------------------------------------------------------
#define B_   32
#define S_   512
#define D_   512
#define H_   8
#define L_   4
#define F_   2048
#define DK_  64
#define MROWS (B_ * S_)            // 16384 token rows

// ---------------------------------------------------------------------------
// Scratch (static device arrays: no allocations allowed)
// ---------------------------------------------------------------------------
__device__ float g_x  [MROWS * D_];
__device__ float g_y  [MROWS * D_];
__device__ float g_kq [MROWS * D_];
__device__ float g_v  [MROWS * D_];
__device__ float g_ctx[MROWS * D_];
__device__ float g_o  [MROWS * D_];
__device__ float g_h  [MROWS * F_];

// ---------------------------------------------------------------------------
// x = q + pe ; y = qa + pe
// ---------------------------------------------------------------------------
__global__ void add_pos_kernel(const float4* __restrict__ q,
                               const float4* __restrict__ qa,
                               const float4* __restrict__ pe,
                               float4* __restrict__ x,
                               float4* __restrict__ y)
{
    int i = blockIdx.x * blockDim.x + threadIdx.x;
    if (i >= MROWS * D_ / 4) return;
    int pi = i % (S_ * D_ / 4);
    float4 p = pe[pi];
    float4 a = q[i];
    a.x += p.x; a.y += p.y; a.z += p.z; a.w += p.w;
    x[i] = a;
    float4 b = qa[i];
    b.x += p.x; b.y += p.y; b.z += p.z; b.w += p.w;
    y[i] = b;
}

// ---------------------------------------------------------------------------
// Tensor-core SGEMM via 3xTF32 (error-compensated): fp32-accurate results.
// C[M,N] = A[M,K] @ W[N,K]^T + bias[N]  (optional ReLU)
// BM=BN=128, BK=16, 256 threads = 8 warps, warp tile 64x32 (m16n8k8 frags).
// smem layout [k][ m ^ SWZ(k) ], SWZ(k) = ((k&3)^((k>>2)&3))<<3:
//   conflict-free for staging stores AND all fragment loads.
// ---------------------------------------------------------------------------
#define MMA_TF32(c, a, b)                                                    \
    asm volatile(                                                            \
        "mma.sync.aligned.m16n8k8.row.col.f32.tf32.tf32.f32 "                \
        "{%0,%1,%2,%3},{%4,%5,%6,%7},{%8,%9},{%0,%1,%2,%3};"                 \
        : "+f"((c)[0]), "+f"((c)[1]), "+f"((c)[2]), "+f"((c)[3])             \
        : "r"((a)[0]), "r"((a)[1]), "r"((a)[2]), "r"((a)[3]),                \
          "r"((b)[0]), "r"((b)[1]))

__device__ __forceinline__ void split_tf32(float v, uint32_t& hi, uint32_t& lo)
{
    uint32_t h = __float_as_uint(v) & 0xFFFFE000u;   // exact tf32 value
    hi = h;
    lo = __float_as_uint(v - __uint_as_float(h));    // residual (|lo| ~ 2^-11 |v|)
}

template <bool RELU>
__global__ void __launch_bounds__(256)
gemm_tc_kernel(const float* __restrict__ A,
               const float* __restrict__ W,
               const float* __restrict__ bias,
               float* __restrict__ C,
               int M, int N, int K)
{
    __shared__ float As[16 * 128];
    __shared__ float Bs[16 * 128];

    const int tid  = threadIdx.x;
    const int lane = tid & 31;
    const int warp = tid >> 5;
    const int wm   = warp & 1;        // warp row (2 x 64)
    const int wn   = warp >> 1;       // warp col (4 x 32)
    const int lq   = lane & 3;        // threadID_in_group (k)
    const int lr   = lane >> 2;       // groupID (m/n)

    const int row0 = blockIdx.y * 128;
    const int col0 = blockIdx.x * 128;

    const float* Aptr = A + (size_t)row0 * K;
    const float* Wptr = W + (size_t)col0 * K;

    // staging assignment: 2 rows x one float4 (4 consecutive k) per matrix
    const int r0_ = tid >> 2;             // 0..63
    const int r1_ = r0_ + 64;
    const int c4_ = (tid & 3) << 2;       // k base: 0,4,8,12
    const int tq  = tid & 3;

    float acc[4][4][4];
#pragma unroll
    for (int mt = 0; mt < 4; mt++)
#pragma unroll
        for (int nt = 0; nt < 4; nt++)
#pragma unroll
            for (int e = 0; e < 4; e++) acc[mt][nt][e] = 0.0f;

    // prefetch stage 0
    float4 pa0 = *(const float4*)(Aptr + (size_t)r0_ * K + c4_);
    float4 pa1 = *(const float4*)(Aptr + (size_t)r1_ * K + c4_);
    float4 pb0 = *(const float4*)(Wptr + (size_t)r0_ * K + c4_);
    float4 pb1 = *(const float4*)(Wptr + (size_t)r1_ * K + c4_);

    for (int k0 = 0; k0 < K; k0 += 16) {
        // ---- stage regs -> smem, swizzled, conflict-free ----
        {
#define STAGE1(Sm, r, v)                                                      \
            Sm[(c4_ + 0) * 128 + ((r) ^ (((0 ^ tq)) << 3))] = v.x;            \
            Sm[(c4_ + 1) * 128 + ((r) ^ (((1 ^ tq)) << 3))] = v.y;            \
            Sm[(c4_ + 2) * 128 + ((r) ^ (((2 ^ tq)) << 3))] = v.z;            \
            Sm[(c4_ + 3) * 128 + ((r) ^ (((3 ^ tq)) << 3))] = v.w;
            STAGE1(As, r0_, pa0)
            STAGE1(As, r1_, pa1)
            STAGE1(Bs, r0_, pb0)
            STAGE1(Bs, r1_, pb1)
#undef STAGE1
        }
        __syncthreads();

        // ---- prefetch next stage ----
        const int kn = k0 + 16;
        if (kn < K) {
            pa0 = *(const float4*)(Aptr + (size_t)r0_ * K + kn + c4_);
            pa1 = *(const float4*)(Aptr + (size_t)r1_ * K + kn + c4_);
            pb0 = *(const float4*)(Wptr + (size_t)r0_ * K + kn + c4_);
            pb1 = *(const float4*)(Wptr + (size_t)r1_ * K + kn + c4_);
        }

        // ---- compute: 2 k-steps of 8 ----
#pragma unroll
        for (int kk = 0; kk < 16; kk += 8) {
            const int kc  = (kk >> 2) & 3;              // 0 or 2
            const int s0  = (lq ^ kc) << 3;
            const int s1  = (lq ^ kc ^ 1) << 3;
            const int kr0 = (kk + lq) * 128;
            const int kr1 = (kk + 4 + lq) * 128;

            // B fragments (4 n-tiles), split hi/lo
            uint32_t bh[4][2], bl[4][2];
#pragma unroll
            for (int nt = 0; nt < 4; nt++) {
                int n = wn * 32 + nt * 8 + lr;
                float v0 = Bs[kr0 + (n ^ s0)];
                float v1 = Bs[kr1 + (n ^ s1)];
                split_tf32(v0, bh[nt][0], bl[nt][0]);
                split_tf32(v1, bh[nt][1], bl[nt][1]);
            }

#pragma unroll
            for (int mt = 0; mt < 4; mt++) {
                int row = wm * 64 + mt * 16 + lr;
                float a0 = As[kr0 + (row ^ s0)];
                float a1 = As[kr0 + ((row + 8) ^ s0)];
                float a2 = As[kr1 + (row ^ s1)];
                float a3 = As[kr1 + ((row + 8) ^ s1)];
                uint32_t ah[4], al[4];
                split_tf32(a0, ah[0], al[0]);
                split_tf32(a1, ah[1], al[1]);
                split_tf32(a2, ah[2], al[2]);
                split_tf32(a3, ah[3], al[3]);
#pragma unroll
                for (int nt = 0; nt < 4; nt++) {
                    MMA_TF32(acc[mt][nt], ah, bl[nt]);   // small terms first
                    MMA_TF32(acc[mt][nt], al, bh[nt]);
                    MMA_TF32(acc[mt][nt], ah, bh[nt]);
                }
            }
        }
        __syncthreads();
    }

    // ---- epilogue: bias (+ReLU) ----
#pragma unroll
    for (int nt = 0; nt < 4; nt++) {
        int c  = col0 + wn * 32 + nt * 8 + 2 * lq;
        float bv0 = bias[c];
        float bv1 = bias[c + 1];
#pragma unroll
        for (int mt = 0; mt < 4; mt++) {
            int r = row0 + wm * 64 + mt * 16 + lr;
            float2 o0, o1;
            o0.x = acc[mt][nt][0] + bv0;
            o0.y = acc[mt][nt][1] + bv1;
            o1.x = acc[mt][nt][2] + bv0;
            o1.y = acc[mt][nt][3] + bv1;
            if (RELU) {
                o0.x = fmaxf(o0.x, 0.0f); o0.y = fmaxf(o0.y, 0.0f);
                o1.x = fmaxf(o1.x, 0.0f); o1.y = fmaxf(o1.y, 0.0f);
            }
            *(float2*)&C[(size_t)r * N + c]       = o0;
            *(float2*)&C[(size_t)(r + 8) * N + c] = o1;
        }
    }
}

// ---------------------------------------------------------------------------
// Fused causal attention (flash-style, online softmax).
// ---------------------------------------------------------------------------
#define ATTN_SMEM ((64 * 64 + 64 * 65 + 64 * 64) * 4)

__global__ void __launch_bounds__(256)
attn_kernel(const float* __restrict__ kq,
            const float* __restrict__ v,
            const float* __restrict__ fr,
            float* __restrict__ ctx)
{
    extern __shared__ float sm[];
    float* Qs  = sm;
    float* KPs = sm + 64 * 64;
    float* Vs  = sm + 64 * 64 + 64 * 65;

    const int qt = blockIdx.x;
    const int h  = blockIdx.y;
    const int b  = blockIdx.z;
    const int tid = threadIdx.x;
    const int ty = tid >> 4;
    const int tx = tid & 15;
    const int s0 = qt * 64;

#pragma unroll
    for (int it = 0; it < 4; it++) {
        int i  = tid + it * 256;
        int r  = i >> 4;
        int c4 = (i & 15) << 2;
        float4 qv = *(const float4*)&kq[((size_t)(b * S_ + s0 + r)) * D_ + h * DK_ + c4];
        Qs[r * 64 + c4 + 0] = qv.x; Qs[r * 64 + c4 + 1] = qv.y;
        Qs[r * 64 + c4 + 2] = qv.z; Qs[r * 64 + c4 + 3] = qv.w;
    }

    float m_i[4], l_i[4], acc[4][4];
#pragma unroll
    for (int i = 0; i < 4; i++) {
        m_i[i] = -1e30f; l_i[i] = 0.0f;
#pragma unroll
        for (int j = 0; j < 4; j++) acc[i][j] = 0.0f;
    }

    float rowf[4];
#pragma unroll
    for (int i = 0; i < 4; i++)
        rowf[i] = 0.125f * fr[b * S_ + s0 + ty * 4 + i];

    for (int kt = 0; kt <= qt; kt++) {
        __syncthreads();
        const int t0 = kt * 64;
#pragma unroll
        for (int it = 0; it < 4; it++) {
            int i  = tid + it * 256;
            int r  = i >> 4;
            int c4 = (i & 15) << 2;
            size_t base = ((size_t)(b * S_ + t0 + r)) * D_ + h * DK_ + c4;
            float4 kk = *(const float4*)&kq[base];
            KPs[r * 65 + c4 + 0] = kk.x; KPs[r * 65 + c4 + 1] = kk.y;
            KPs[r * 65 + c4 + 2] = kk.z; KPs[r * 65 + c4 + 3] = kk.w;
            float4 vv = *(const float4*)&v[base];
            Vs[r * 64 + c4 + 0] = vv.x; Vs[r * 64 + c4 + 1] = vv.y;
            Vs[r * 64 + c4 + 2] = vv.z; Vs[r * 64 + c4 + 3] = vv.w;
        }
        __syncthreads();

        float sc[4][4];
#pragma unroll
        for (int i = 0; i < 4; i++)
#pragma unroll
            for (int j = 0; j < 4; j++) sc[i][j] = 0.0f;

#pragma unroll 8
        for (int k = 0; k < 64; k++) {
            float qreg[4], kreg[4];
#pragma unroll
            for (int i = 0; i < 4; i++) qreg[i] = Qs[(ty * 4 + i) * 64 + k];
#pragma unroll
            for (int j = 0; j < 4; j++) kreg[j] = KPs[(tx * 4 + j) * 65 + k];
#pragma unroll
            for (int i = 0; i < 4; i++)
#pragma unroll
                for (int j = 0; j < 4; j++)
                    sc[i][j] += qreg[i] * kreg[j];
        }

        const bool diag = (kt == qt);
#pragma unroll
        for (int i = 0; i < 4; i++)
#pragma unroll
            for (int j = 0; j < 4; j++) {
                sc[i][j] *= rowf[i];
                if (diag && (tx * 4 + j >= ty * 4 + i)) sc[i][j] = -1e30f;
            }

        float mt[4];
#pragma unroll
        for (int i = 0; i < 4; i++)
            mt[i] = fmaxf(fmaxf(sc[i][0], sc[i][1]), fmaxf(sc[i][2], sc[i][3]));
#pragma unroll
        for (int off = 8; off >= 1; off >>= 1)
#pragma unroll
            for (int i = 0; i < 4; i++)
                mt[i] = fmaxf(mt[i], __shfl_xor_sync(0xffffffffu, mt[i], off));

        float p[4][4], rs[4];
#pragma unroll
        for (int i = 0; i < 4; i++) {
            float mnew  = fmaxf(m_i[i], mt[i]);
            float alpha = __expf(m_i[i] - mnew);
            m_i[i] = mnew;
            rs[i]  = 0.0f;
#pragma unroll
            for (int j = 0; j < 4; j++) {
                p[i][j] = __expf(sc[i][j] - mnew);
                rs[i]  += p[i][j];
            }
            l_i[i] *= alpha;
#pragma unroll
            for (int j = 0; j < 4; j++) acc[i][j] *= alpha;
        }
#pragma unroll
        for (int off = 8; off >= 1; off >>= 1)
#pragma unroll
            for (int i = 0; i < 4; i++)
                rs[i] += __shfl_xor_sync(0xffffffffu, rs[i], off);
#pragma unroll
        for (int i = 0; i < 4; i++) l_i[i] += rs[i];

        __syncthreads();
#pragma unroll
        for (int i = 0; i < 4; i++)
#pragma unroll
            for (int j = 0; j < 4; j++)
                KPs[(ty * 4 + i) * 65 + tx * 4 + j] = p[i][j];
        __syncthreads();

#pragma unroll 8
        for (int k = 0; k < 64; k++) {
            float pr[4], vr[4];
#pragma unroll
            for (int i = 0; i < 4; i++) pr[i] = KPs[(ty * 4 + i) * 65 + k];
#pragma unroll
            for (int j = 0; j < 4; j++) vr[j] = Vs[k * 64 + tx * 4 + j];
#pragma unroll
            for (int i = 0; i < 4; i++)
#pragma unroll
                for (int j = 0; j < 4; j++)
                    acc[i][j] += pr[i] * vr[j];
        }
    }

#pragma unroll
    for (int i = 0; i < 4; i++) {
        int srow  = s0 + ty * 4 + i;
        float inv = 1.0f / l_i[i];
        float4 o;
        o.x = acc[i][0] * inv; o.y = acc[i][1] * inv;
        o.z = acc[i][2] * inv; o.w = acc[i][3] * inv;
        if (srow == 0) { o.x = 0.0f; o.y = 0.0f; o.z = 0.0f; o.w = 0.0f; }
        *(float4*)&ctx[((size_t)(b * S_ + srow)) * D_ + h * DK_ + tx * 4] = o;
    }
}

// ---------------------------------------------------------------------------
// xout = LayerNorm(xin + res) * g + beta
// ---------------------------------------------------------------------------
__global__ void __launch_bounds__(128)
add_ln_kernel(const float* __restrict__ xin,
              const float* __restrict__ res,
              const float* __restrict__ g,
              const float* __restrict__ beta,
              float* __restrict__ xout)
{
    const int row = blockIdx.x;
    const int tid = threadIdx.x;

    float4 a = ((const float4*)(xin + (size_t)row * D_))[tid];
    float4 b = ((const float4*)(res + (size_t)row * D_))[tid];
    float v0 = a.x + b.x, v1 = a.y + b.y, v2 = a.z + b.z, v3 = a.w + b.w;

    float s  = v0 + v1 + v2 + v3;
    float sq = v0 * v0 + v1 * v1 + v2 * v2 + v3 * v3;
#pragma unroll
    for (int off = 16; off >= 1; off >>= 1) {
        s  += __shfl_xor_sync(0xffffffffu, s,  off);
        sq += __shfl_xor_sync(0xffffffffu, sq, off);
    }
    __shared__ float ss[4], ssq[4];
    int w = tid >> 5, lane = tid & 31;
    if (lane == 0) { ss[w] = s; ssq[w] = sq; }
    __syncthreads();
    s  = ss[0]  + ss[1]  + ss[2]  + ss[3];
    sq = ssq[0] + ssq[1] + ssq[2] + ssq[3];

    const float mu   = s * (1.0f / (float)D_);
    const float var  = sq * (1.0f / (float)D_) - mu * mu;
    const float rstd = rsqrtf(var + 1e-5f);

    float4 gg = ((const float4*)g)[tid];
    float4 bb = ((const float4*)beta)[tid];
    float4 o;
    o.x = (v0 - mu) * rstd * gg.x + bb.x;
    o.y = (v1 - mu) * rstd * gg.y + bb.y;
    o.z = (v2 - mu) * rstd * gg.z + bb.z;
    o.w = (v3 - mu) * rstd * gg.w + bb.w;
    ((float4*)(xout + (size_t)row * D_))[tid] = o;
}

// ---------------------------------------------------------------------------
// Orchestration
// ---------------------------------------------------------------------------
extern "C" void kernel_launch(void* const* d_in, const int* in_sizes, int n_in,
                              void* d_out, int out_size)
{
    const float* q   = (const float*)d_in[0];
    const float* qa  = (const float*)d_in[1];
    const float* fr  = (const float*)d_in[2];
    const float* pe  = (const float*)d_in[3];
    const float* Wk  = (const float*)d_in[4];
    const float* bk  = (const float*)d_in[5];
    const float* Wv  = (const float*)d_in[6];
    const float* bv  = (const float*)d_in[7];
    const float* Wo  = (const float*)d_in[8];
    const float* bo  = (const float*)d_in[9];
    const float* W1  = (const float*)d_in[10];
    const float* b1  = (const float*)d_in[11];
    const float* W2  = (const float*)d_in[12];
    const float* b2  = (const float*)d_in[13];
    const float* g1  = (const float*)d_in[14];
    const float* be1 = (const float*)d_in[15];
    const float* g2  = (const float*)d_in[16];
    const float* be2 = (const float*)d_in[17];
    float* out = (float*)d_out;

    float *x, *y, *kqb, *vb, *ctxb, *ob, *hb;
    cudaGetSymbolAddress((void**)&x,    g_x);
    cudaGetSymbolAddress((void**)&y,    g_y);
    cudaGetSymbolAddress((void**)&kqb,  g_kq);
    cudaGetSymbolAddress((void**)&vb,   g_v);
    cudaGetSymbolAddress((void**)&ctxb, g_ctx);
    cudaGetSymbolAddress((void**)&ob,   g_o);
    cudaGetSymbolAddress((void**)&hb,   g_h);

    cudaFuncSetAttribute(attn_kernel,
                         cudaFuncAttributeMaxDynamicSharedMemorySize, ATTN_SMEM);

    {
        int n4 = MROWS * D_ / 4;
        add_pos_kernel<<<(n4 + 255) / 256, 256>>>(
            (const float4*)q, (const float4*)qa, (const float4*)pe,
            (float4*)x, (float4*)y);
    }

    const dim3 gD(D_ / 128, MROWS / 128);   // (4, 128)
    const dim3 gF(F_ / 128, MROWS / 128);   // (16, 128)
    const dim3 gA(S_ / 64, H_, B_);         // (8, 8, 32)

    for (int l = 0; l < L_; l++) {
        const size_t wDD = (size_t)l * D_ * D_;
        const size_t wFD = (size_t)l * F_ * D_;

        gemm_tc_kernel<false><<<gD, 256>>>(x, Wk + wDD, bk + l * D_, kqb, MROWS, D_, D_);
        gemm_tc_kernel<false><<<gD, 256>>>(y, Wv + wDD, bv + l * D_, vb,  MROWS, D_, D_);
        attn_kernel<<<gA, 256, ATTN_SMEM>>>(kqb, vb, fr, ctxb);
        gemm_tc_kernel<false><<<gD, 256>>>(ctxb, Wo + wDD, bo + l * D_, ob, MROWS, D_, D_);
        add_ln_kernel<<<MROWS, 128>>>(x, ob, g1 + l * D_, be1 + l * D_, x);
        gemm_tc_kernel<true ><<<gF, 256>>>(x, W1 + wFD, b1 + l * F_, hb, MROWS, F_, D_);
        gemm_tc_kernel<false><<<gD, 256>>>(hb, W2 + wFD, b2 + l * D_, ob, MROWS, D_, F_);
        add_ln_kernel<<<MROWS, 128>>>(x, ob, g2 + l * D_, be2 + l * D_,
                                      (l == L_ - 1) ? out : x);
    }
}

// round 8
// speedup vs baseline: 1.7795x; 1.1705x over previous
#include <cuda_runtime.h>
#include <cstdint>
#include <cstddef>

// ---------------------------------------------------------------------------
// Problem constants
// ---------------------------------------------------------------------------
#define B_   32
#define S_   512
#define D_   512
#define H_   8
#define L_   4
#define F_   2048
#define DK_  64
#define MROWS (B_ * S_)            // 16384 token rows

// ---------------------------------------------------------------------------
// Scratch (static device arrays: no allocations allowed)
// ---------------------------------------------------------------------------
__device__ float g_x  [MROWS * D_];
__device__ float g_y  [MROWS * D_];
__device__ float g_kq [MROWS * D_];
__device__ float g_v  [MROWS * D_];
__device__ float g_ctx[MROWS * D_];
__device__ float g_o  [MROWS * D_];
__device__ float g_h  [MROWS * F_];

// ---------------------------------------------------------------------------
// x = q + pe ; y = qa + pe
// ---------------------------------------------------------------------------
__global__ void add_pos_kernel(const float4* __restrict__ q,
                               const float4* __restrict__ qa,
                               const float4* __restrict__ pe,
                               float4* __restrict__ x,
                               float4* __restrict__ y)
{
    int i = blockIdx.x * blockDim.x + threadIdx.x;
    if (i >= MROWS * D_ / 4) return;
    int pi = i % (S_ * D_ / 4);
    float4 p = pe[pi];
    float4 a = q[i];
    a.x += p.x; a.y += p.y; a.z += p.z; a.w += p.w;
    x[i] = a;
    float4 b = qa[i];
    b.x += p.x; b.y += p.y; b.z += p.z; b.w += p.w;
    y[i] = b;
}

// ---------------------------------------------------------------------------
// Tensor-core SGEMM via split-BF16 x3 (error-compensated, ~1.5e-4 e2e).
//   a = a_hi + a_lo (bf16 each); acc += ah*bh + ah*bl + al*bh  (drop al*bl)
// C[M,N] = A[M,K] @ W[N,K]^T + bias[N]  (optional ReLU)
// BM=BN=128, BK=16, 256 threads = 8 warps, warp tile 64x32 (m16n8k16 frags).
// smem: 4 planes (Ah/Al/Bh/Bl) of [8 kpairs][128 rows] u32 (bf16x2),
//   double-buffered; swizzle idx = p*128 + (row ^ ((p&3)<<3)):
//   conflict-free for all fragment loads.
// Conversion fp32->bf16 hi/lo happens ONCE at staging (not in inner loop).
// ---------------------------------------------------------------------------
#define MMA_BF16(c, a, b)                                                    \
    asm volatile(                                                            \
        "mma.sync.aligned.m16n8k16.row.col.f32.bf16.bf16.f32 "               \
        "{%0,%1,%2,%3},{%4,%5,%6,%7},{%8,%9},{%0,%1,%2,%3};"                 \
        : "+f"((c)[0]), "+f"((c)[1]), "+f"((c)[2]), "+f"((c)[3])             \
        : "r"((a)[0]), "r"((a)[1]), "r"((a)[2]), "r"((a)[3]),                \
          "r"((b)[0]), "r"((b)[1]))

// pack two fp32 -> bf16x2 (lo in low half, hi in high half)
__device__ __forceinline__ uint32_t pack_bf16x2(float lo, float hi)
{
    uint32_t r;
    asm("cvt.rn.bf16x2.f32 %0, %1, %2;" : "=r"(r) : "f"(hi), "f"(lo));
    return r;
}

#define SWIZ(p, r) (((p) << 7) + ((r) ^ (((p) & 3) << 3)))

// split float4 (4 consecutive k) into 2 hi-pairs + 2 lo-pairs and store
__device__ __forceinline__ void stage_split(uint32_t* __restrict__ hiArr,
                                            uint32_t* __restrict__ loArr,
                                            int p0, int r, float4 v)
{
    uint32_t h01 = pack_bf16x2(v.x, v.y);
    float fx = __uint_as_float(h01 << 16);
    float fy = __uint_as_float(h01 & 0xFFFF0000u);
    uint32_t l01 = pack_bf16x2(v.x - fx, v.y - fy);
    uint32_t h23 = pack_bf16x2(v.z, v.w);
    float fz = __uint_as_float(h23 << 16);
    float fw = __uint_as_float(h23 & 0xFFFF0000u);
    uint32_t l23 = pack_bf16x2(v.z - fz, v.w - fw);
    hiArr[SWIZ(p0, r)]     = h01;
    loArr[SWIZ(p0, r)]     = l01;
    hiArr[SWIZ(p0 + 1, r)] = h23;
    loArr[SWIZ(p0 + 1, r)] = l23;
}

template <bool RELU>
__global__ void __launch_bounds__(256)
gemm_tc_kernel(const float* __restrict__ A,
               const float* __restrict__ W,
               const float* __restrict__ bias,
               float* __restrict__ C,
               int M, int N, int K)
{
    // [buf][hi=0/lo=1][8*128]
    __shared__ uint32_t sA[2][2][8 * 128];
    __shared__ uint32_t sB[2][2][8 * 128];

    const int tid  = threadIdx.x;
    const int lane = tid & 31;
    const int warp = tid >> 5;
    const int wm   = warp & 1;        // warp row (2 x 64)
    const int wn   = warp >> 1;       // warp col (4 x 32)
    const int lq   = lane & 3;        // kpair selector
    const int lr   = lane >> 2;       // groupID (m/n)

    const int row0 = blockIdx.y * 128;
    const int col0 = blockIdx.x * 128;

    const float* Aptr = A + (size_t)row0 * K;
    const float* Wptr = W + (size_t)col0 * K;

    // staging assignment: 2 rows x one float4 (4 consecutive k) per matrix
    const int r0_ = tid >> 2;             // 0..63
    const int r1_ = r0_ + 64;
    const int tq  = tid & 3;
    const int c4_ = tq << 2;              // k base: 0,4,8,12
    const int p0_ = tq << 1;              // kpair base: 0,2,4,6

    float acc[4][4][4];
#pragma unroll
    for (int mt = 0; mt < 4; mt++)
#pragma unroll
        for (int nt = 0; nt < 4; nt++)
#pragma unroll
            for (int e = 0; e < 4; e++) acc[mt][nt][e] = 0.0f;

    const int nstages = K >> 4;

    // prologue: load + stage buffer 0
    float4 pa0 = *(const float4*)(Aptr + (size_t)r0_ * K + c4_);
    float4 pa1 = *(const float4*)(Aptr + (size_t)r1_ * K + c4_);
    float4 pb0 = *(const float4*)(Wptr + (size_t)r0_ * K + c4_);
    float4 pb1 = *(const float4*)(Wptr + (size_t)r1_ * K + c4_);
    stage_split(sA[0][0], sA[0][1], p0_, r0_, pa0);
    stage_split(sA[0][0], sA[0][1], p0_, r1_, pa1);
    stage_split(sB[0][0], sB[0][1], p0_, r0_, pb0);
    stage_split(sB[0][0], sB[0][1], p0_, r1_, pb1);
    __syncthreads();

    const int pA = lq;        // kpair for first half of frag
    const int pB = lq + 4;    // kpair for second half

    for (int i = 0; i < nstages; i++) {
        const int cur = i & 1;
        const bool more = (i + 1 < nstages);

        // prefetch next stage (gmem) while computing this one
        if (more) {
            const size_t koff = (size_t)(i + 1) << 4;
            pa0 = *(const float4*)(Aptr + (size_t)r0_ * K + koff + c4_);
            pa1 = *(const float4*)(Aptr + (size_t)r1_ * K + koff + c4_);
            pb0 = *(const float4*)(Wptr + (size_t)r0_ * K + koff + c4_);
            pb1 = *(const float4*)(Wptr + (size_t)r1_ * K + koff + c4_);
        }

        const uint32_t* Ah = sA[cur][0];
        const uint32_t* Al = sA[cur][1];
        const uint32_t* Bh = sB[cur][0];
        const uint32_t* Bl = sB[cur][1];

        // B fragments (4 n-tiles)
        uint32_t bh[4][2], bl[4][2];
#pragma unroll
        for (int nt = 0; nt < 4; nt++) {
            int n = wn * 32 + nt * 8 + lr;
            bh[nt][0] = Bh[SWIZ(pA, n)];
            bh[nt][1] = Bh[SWIZ(pB, n)];
            bl[nt][0] = Bl[SWIZ(pA, n)];
            bl[nt][1] = Bl[SWIZ(pB, n)];
        }

#pragma unroll
        for (int mt = 0; mt < 4; mt++) {
            int r = wm * 64 + mt * 16 + lr;
            uint32_t ah[4], al[4];
            ah[0] = Ah[SWIZ(pA, r)];
            ah[1] = Ah[SWIZ(pA, r + 8)];
            ah[2] = Ah[SWIZ(pB, r)];
            ah[3] = Ah[SWIZ(pB, r + 8)];
            al[0] = Al[SWIZ(pA, r)];
            al[1] = Al[SWIZ(pA, r + 8)];
            al[2] = Al[SWIZ(pB, r)];
            al[3] = Al[SWIZ(pB, r + 8)];
#pragma unroll
            for (int nt = 0; nt < 4; nt++) {
                MMA_BF16(acc[mt][nt], ah, bl[nt]);   // small terms first
                MMA_BF16(acc[mt][nt], al, bh[nt]);
                MMA_BF16(acc[mt][nt], ah, bh[nt]);
            }
        }

        // stage next into the other buffer (read of that buffer finished
        // before the barrier that ended iteration i-1)
        if (more) {
            const int nxt = cur ^ 1;
            stage_split(sA[nxt][0], sA[nxt][1], p0_, r0_, pa0);
            stage_split(sA[nxt][0], sA[nxt][1], p0_, r1_, pa1);
            stage_split(sB[nxt][0], sB[nxt][1], p0_, r0_, pb0);
            stage_split(sB[nxt][0], sB[nxt][1], p0_, r1_, pb1);
        }
        __syncthreads();
    }

    // ---- epilogue: bias (+ReLU) ----
#pragma unroll
    for (int nt = 0; nt < 4; nt++) {
        int c  = col0 + wn * 32 + nt * 8 + 2 * lq;
        float bv0 = bias[c];
        float bv1 = bias[c + 1];
#pragma unroll
        for (int mt = 0; mt < 4; mt++) {
            int r = row0 + wm * 64 + mt * 16 + lr;
            float2 o0, o1;
            o0.x = acc[mt][nt][0] + bv0;
            o0.y = acc[mt][nt][1] + bv1;
            o1.x = acc[mt][nt][2] + bv0;
            o1.y = acc[mt][nt][3] + bv1;
            if (RELU) {
                o0.x = fmaxf(o0.x, 0.0f); o0.y = fmaxf(o0.y, 0.0f);
                o1.x = fmaxf(o1.x, 0.0f); o1.y = fmaxf(o1.y, 0.0f);
            }
            *(float2*)&C[(size_t)r * N + c]       = o0;
            *(float2*)&C[(size_t)(r + 8) * N + c] = o1;
        }
    }
}

// ---------------------------------------------------------------------------
// Fused causal attention (flash-style, online softmax) — unchanged.
// ---------------------------------------------------------------------------
#define ATTN_SMEM ((64 * 64 + 64 * 65 + 64 * 64) * 4)

__global__ void __launch_bounds__(256)
attn_kernel(const float* __restrict__ kq,
            const float* __restrict__ v,
            const float* __restrict__ fr,
            float* __restrict__ ctx)
{
    extern __shared__ float sm[];
    float* Qs  = sm;
    float* KPs = sm + 64 * 64;
    float* Vs  = sm + 64 * 64 + 64 * 65;

    const int qt = blockIdx.x;
    const int h  = blockIdx.y;
    const int b  = blockIdx.z;
    const int tid = threadIdx.x;
    const int ty = tid >> 4;
    const int tx = tid & 15;
    const int s0 = qt * 64;

#pragma unroll
    for (int it = 0; it < 4; it++) {
        int i  = tid + it * 256;
        int r  = i >> 4;
        int c4 = (i & 15) << 2;
        float4 qv = *(const float4*)&kq[((size_t)(b * S_ + s0 + r)) * D_ + h * DK_ + c4];
        Qs[r * 64 + c4 + 0] = qv.x; Qs[r * 64 + c4 + 1] = qv.y;
        Qs[r * 64 + c4 + 2] = qv.z; Qs[r * 64 + c4 + 3] = qv.w;
    }

    float m_i[4], l_i[4], acc[4][4];
#pragma unroll
    for (int i = 0; i < 4; i++) {
        m_i[i] = -1e30f; l_i[i] = 0.0f;
#pragma unroll
        for (int j = 0; j < 4; j++) acc[i][j] = 0.0f;
    }

    float rowf[4];
#pragma unroll
    for (int i = 0; i < 4; i++)
        rowf[i] = 0.125f * fr[b * S_ + s0 + ty * 4 + i];

    for (int kt = 0; kt <= qt; kt++) {
        __syncthreads();
        const int t0 = kt * 64;
#pragma unroll
        for (int it = 0; it < 4; it++) {
            int i  = tid + it * 256;
            int r  = i >> 4;
            int c4 = (i & 15) << 2;
            size_t base = ((size_t)(b * S_ + t0 + r)) * D_ + h * DK_ + c4;
            float4 kk = *(const float4*)&kq[base];
            KPs[r * 65 + c4 + 0] = kk.x; KPs[r * 65 + c4 + 1] = kk.y;
            KPs[r * 65 + c4 + 2] = kk.z; KPs[r * 65 + c4 + 3] = kk.w;
            float4 vv = *(const float4*)&v[base];
            Vs[r * 64 + c4 + 0] = vv.x; Vs[r * 64 + c4 + 1] = vv.y;
            Vs[r * 64 + c4 + 2] = vv.z; Vs[r * 64 + c4 + 3] = vv.w;
        }
        __syncthreads();

        float sc[4][4];
#pragma unroll
        for (int i = 0; i < 4; i++)
#pragma unroll
            for (int j = 0; j < 4; j++) sc[i][j] = 0.0f;

#pragma unroll 8
        for (int k = 0; k < 64; k++) {
            float qreg[4], kreg[4];
#pragma unroll
            for (int i = 0; i < 4; i++) qreg[i] = Qs[(ty * 4 + i) * 64 + k];
#pragma unroll
            for (int j = 0; j < 4; j++) kreg[j] = KPs[(tx * 4 + j) * 65 + k];
#pragma unroll
            for (int i = 0; i < 4; i++)
#pragma unroll
                for (int j = 0; j < 4; j++)
                    sc[i][j] += qreg[i] * kreg[j];
        }

        const bool diag = (kt == qt);
#pragma unroll
        for (int i = 0; i < 4; i++)
#pragma unroll
            for (int j = 0; j < 4; j++) {
                sc[i][j] *= rowf[i];
                if (diag && (tx * 4 + j >= ty * 4 + i)) sc[i][j] = -1e30f;
            }

        float mt[4];
#pragma unroll
        for (int i = 0; i < 4; i++)
            mt[i] = fmaxf(fmaxf(sc[i][0], sc[i][1]), fmaxf(sc[i][2], sc[i][3]));
#pragma unroll
        for (int off = 8; off >= 1; off >>= 1)
#pragma unroll
            for (int i = 0; i < 4; i++)
                mt[i] = fmaxf(mt[i], __shfl_xor_sync(0xffffffffu, mt[i], off));

        float p[4][4], rs[4];
#pragma unroll
        for (int i = 0; i < 4; i++) {
            float mnew  = fmaxf(m_i[i], mt[i]);
            float alpha = __expf(m_i[i] - mnew);
            m_i[i] = mnew;
            rs[i]  = 0.0f;
#pragma unroll
            for (int j = 0; j < 4; j++) {
                p[i][j] = __expf(sc[i][j] - mnew);
                rs[i]  += p[i][j];
            }
            l_i[i] *= alpha;
#pragma unroll
            for (int j = 0; j < 4; j++) acc[i][j] *= alpha;
        }
#pragma unroll
        for (int off = 8; off >= 1; off >>= 1)
#pragma unroll
            for (int i = 0; i < 4; i++)
                rs[i] += __shfl_xor_sync(0xffffffffu, rs[i], off);
#pragma unroll
        for (int i = 0; i < 4; i++) l_i[i] += rs[i];

        __syncthreads();
#pragma unroll
        for (int i = 0; i < 4; i++)
#pragma unroll
            for (int j = 0; j < 4; j++)
                KPs[(ty * 4 + i) * 65 + tx * 4 + j] = p[i][j];
        __syncthreads();

#pragma unroll 8
        for (int k = 0; k < 64; k++) {
            float pr[4], vr[4];
#pragma unroll
            for (int i = 0; i < 4; i++) pr[i] = KPs[(ty * 4 + i) * 65 + k];
#pragma unroll
            for (int j = 0; j < 4; j++) vr[j] = Vs[k * 64 + tx * 4 + j];
#pragma unroll
            for (int i = 0; i < 4; i++)
#pragma unroll
                for (int j = 0; j < 4; j++)
                    acc[i][j] += pr[i] * vr[j];
        }
    }

#pragma unroll
    for (int i = 0; i < 4; i++) {
        int srow  = s0 + ty * 4 + i;
        float inv = 1.0f / l_i[i];
        float4 o;
        o.x = acc[i][0] * inv; o.y = acc[i][1] * inv;
        o.z = acc[i][2] * inv; o.w = acc[i][3] * inv;
        if (srow == 0) { o.x = 0.0f; o.y = 0.0f; o.z = 0.0f; o.w = 0.0f; }
        *(float4*)&ctx[((size_t)(b * S_ + srow)) * D_ + h * DK_ + tx * 4] = o;
    }
}

// ---------------------------------------------------------------------------
// xout = LayerNorm(xin + res) * g + beta
// ---------------------------------------------------------------------------
__global__ void __launch_bounds__(128)
add_ln_kernel(const float* __restrict__ xin,
              const float* __restrict__ res,
              const float* __restrict__ g,
              const float* __restrict__ beta,
              float* __restrict__ xout)
{
    const int row = blockIdx.x;
    const int tid = threadIdx.x;

    float4 a = ((const float4*)(xin + (size_t)row * D_))[tid];
    float4 b = ((const float4*)(res + (size_t)row * D_))[tid];
    float v0 = a.x + b.x, v1 = a.y + b.y, v2 = a.z + b.z, v3 = a.w + b.w;

    float s  = v0 + v1 + v2 + v3;
    float sq = v0 * v0 + v1 * v1 + v2 * v2 + v3 * v3;
#pragma unroll
    for (int off = 16; off >= 1; off >>= 1) {
        s  += __shfl_xor_sync(0xffffffffu, s,  off);
        sq += __shfl_xor_sync(0xffffffffu, sq, off);
    }
    __shared__ float ss[4], ssq[4];
    int w = tid >> 5, lane = tid & 31;
    if (lane == 0) { ss[w] = s; ssq[w] = sq; }
    __syncthreads();
    s  = ss[0]  + ss[1]  + ss[2]  + ss[3];
    sq = ssq[0] + ssq[1] + ssq[2] + ssq[3];

    const float mu   = s * (1.0f / (float)D_);
    const float var  = sq * (1.0f / (float)D_) - mu * mu;
    const float rstd = rsqrtf(var + 1e-5f);

    float4 gg = ((const float4*)g)[tid];
    float4 bb = ((const float4*)beta)[tid];
    float4 o;
    o.x = (v0 - mu) * rstd * gg.x + bb.x;
    o.y = (v1 - mu) * rstd * gg.y + bb.y;
    o.z = (v2 - mu) * rstd * gg.z + bb.z;
    o.w = (v3 - mu) * rstd * gg.w + bb.w;
    ((float4*)(xout + (size_t)row * D_))[tid] = o;
}

// ---------------------------------------------------------------------------
// Orchestration
// ---------------------------------------------------------------------------
extern "C" void kernel_launch(void* const* d_in, const int* in_sizes, int n_in,
                              void* d_out, int out_size)
{
    const float* q   = (const float*)d_in[0];
    const float* qa  = (const float*)d_in[1];
    const float* fr  = (const float*)d_in[2];
    const float* pe  = (const float*)d_in[3];
    const float* Wk  = (const float*)d_in[4];
    const float* bk  = (const float*)d_in[5];
    const float* Wv  = (const float*)d_in[6];
    const float* bv  = (const float*)d_in[7];
    const float* Wo  = (const float*)d_in[8];
    const float* bo  = (const float*)d_in[9];
    const float* W1  = (const float*)d_in[10];
    const float* b1  = (const float*)d_in[11];
    const float* W2  = (const float*)d_in[12];
    const float* b2  = (const float*)d_in[13];
    const float* g1  = (const float*)d_in[14];
    const float* be1 = (const float*)d_in[15];
    const float* g2  = (const float*)d_in[16];
    const float* be2 = (const float*)d_in[17];
    float* out = (float*)d_out;

    float *x, *y, *kqb, *vb, *ctxb, *ob, *hb;
    cudaGetSymbolAddress((void**)&x,    g_x);
    cudaGetSymbolAddress((void**)&y,    g_y);
    cudaGetSymbolAddress((void**)&kqb,  g_kq);
    cudaGetSymbolAddress((void**)&vb,   g_v);
    cudaGetSymbolAddress((void**)&ctxb, g_ctx);
    cudaGetSymbolAddress((void**)&ob,   g_o);
    cudaGetSymbolAddress((void**)&hb,   g_h);

    cudaFuncSetAttribute(attn_kernel,
                         cudaFuncAttributeMaxDynamicSharedMemorySize, ATTN_SMEM);

    {
        int n4 = MROWS * D_ / 4;
        add_pos_kernel<<<(n4 + 255) / 256, 256>>>(
            (const float4*)q, (const float4*)qa, (const float4*)pe,
            (float4*)x, (float4*)y);
    }

    const dim3 gD(D_ / 128, MROWS / 128);   // (4, 128)
    const dim3 gF(F_ / 128, MROWS / 128);   // (16, 128)
    const dim3 gA(S_ / 64, H_, B_);         // (8, 8, 32)

    for (int l = 0; l < L_; l++) {
        const size_t wDD = (size_t)l * D_ * D_;
        const size_t wFD = (size_t)l * F_ * D_;

        gemm_tc_kernel<false><<<gD, 256>>>(x, Wk + wDD, bk + l * D_, kqb, MROWS, D_, D_);
        gemm_tc_kernel<false><<<gD, 256>>>(y, Wv + wDD, bv + l * D_, vb,  MROWS, D_, D_);
        attn_kernel<<<gA, 256, ATTN_SMEM>>>(kqb, vb, fr, ctxb);
        gemm_tc_kernel<false><<<gD, 256>>>(ctxb, Wo + wDD, bo + l * D_, ob, MROWS, D_, D_);
        add_ln_kernel<<<MROWS, 128>>>(x, ob, g1 + l * D_, be1 + l * D_, x);
        gemm_tc_kernel<true ><<<gF, 256>>>(x, W1 + wFD, b1 + l * F_, hb, MROWS, F_, D_);
        gemm_tc_kernel<false><<<gD, 256>>>(hb, W2 + wFD, b2 + l * D_, ob, MROWS, D_, F_);
        add_ln_kernel<<<MROWS, 128>>>(x, ob, g2 + l * D_, be2 + l * D_,
                                      (l == L_ - 1) ? out : x);
    }
}

// round 11
// speedup vs baseline: 1.9309x; 1.0851x over previous
#include <cuda_runtime.h>
#include <cstdint>
#include <cstddef>

// ---------------------------------------------------------------------------
// Problem constants
// ---------------------------------------------------------------------------
#define B_   32
#define S_   512
#define D_   512
#define H_   8
#define L_   4
#define F_   2048
#define DK_  64
#define MROWS (B_ * S_)            // 16384 token rows

// ---------------------------------------------------------------------------
// Scratch (static device arrays: no allocations allowed)
// ---------------------------------------------------------------------------
__device__ float g_x  [MROWS * D_];
__device__ float g_y  [MROWS * D_];
__device__ float g_kq [MROWS * D_];
__device__ float g_v  [MROWS * D_];
__device__ float g_ctx[MROWS * D_];
__device__ float g_o  [MROWS * D_];
__device__ float g_h  [MROWS * F_];

// ---------------------------------------------------------------------------
// Common helpers: bf16x2 packing + hi/lo split
// ---------------------------------------------------------------------------
#define MMA_BF16(c, a, b)                                                    \
    asm volatile(                                                            \
        "mma.sync.aligned.m16n8k16.row.col.f32.bf16.bf16.f32 "               \
        "{%0,%1,%2,%3},{%4,%5,%6,%7},{%8,%9},{%0,%1,%2,%3};"                 \
        : "+f"((c)[0]), "+f"((c)[1]), "+f"((c)[2]), "+f"((c)[3])             \
        : "r"((a)[0]), "r"((a)[1]), "r"((a)[2]), "r"((a)[3]),                \
          "r"((b)[0]), "r"((b)[1]))

// pack two fp32 -> bf16x2 (first arg in low half, second in high half)
__device__ __forceinline__ uint32_t pack_bf16x2(float lo, float hi)
{
    uint32_t r;
    asm("cvt.rn.bf16x2.f32 %0, %1, %2;" : "=r"(r) : "f"(hi), "f"(lo));
    return r;
}

// split a pair of fp32 into hi/lo bf16x2 words
__device__ __forceinline__ void split2(float x, float y,
                                       uint32_t& hi, uint32_t& lo)
{
    hi = pack_bf16x2(x, y);
    float fx = __uint_as_float(hi << 16);
    float fy = __uint_as_float(hi & 0xFFFF0000u);
    lo = pack_bf16x2(x - fx, y - fy);
}

// ---------------------------------------------------------------------------
// x = q + pe ; y = qa + pe
// ---------------------------------------------------------------------------
__global__ void add_pos_kernel(const float4* __restrict__ q,
                               const float4* __restrict__ qa,
                               const float4* __restrict__ pe,
                               float4* __restrict__ x,
                               float4* __restrict__ y)
{
    int i = blockIdx.x * blockDim.x + threadIdx.x;
    if (i >= MROWS * D_ / 4) return;
    int pi = i % (S_ * D_ / 4);
    float4 p = pe[pi];
    float4 a = q[i];
    a.x += p.x; a.y += p.y; a.z += p.z; a.w += p.w;
    x[i] = a;
    float4 b = qa[i];
    b.x += p.x; b.y += p.y; b.z += p.z; b.w += p.w;
    y[i] = b;
}

// ---------------------------------------------------------------------------
// Tensor-core SGEMM via split-BF16 x3 — unchanged from R8 (passed, 5.5e-6).
// ---------------------------------------------------------------------------
#define SWIZ(p, r) (((p) << 7) + ((r) ^ (((p) & 3) << 3)))

__device__ __forceinline__ void stage_split(uint32_t* __restrict__ hiArr,
                                            uint32_t* __restrict__ loArr,
                                            int p0, int r, float4 v)
{
    uint32_t h01, l01, h23, l23;
    split2(v.x, v.y, h01, l01);
    split2(v.z, v.w, h23, l23);
    hiArr[SWIZ(p0, r)]     = h01;
    loArr[SWIZ(p0, r)]     = l01;
    hiArr[SWIZ(p0 + 1, r)] = h23;
    loArr[SWIZ(p0 + 1, r)] = l23;
}

template <bool RELU>
__global__ void __launch_bounds__(256)
gemm_tc_kernel(const float* __restrict__ A,
               const float* __restrict__ W,
               const float* __restrict__ bias,
               float* __restrict__ C,
               int M, int N, int K)
{
    __shared__ uint32_t sA[2][2][8 * 128];
    __shared__ uint32_t sB[2][2][8 * 128];

    const int tid  = threadIdx.x;
    const int lane = tid & 31;
    const int warp = tid >> 5;
    const int wm   = warp & 1;
    const int wn   = warp >> 1;
    const int lq   = lane & 3;
    const int lr   = lane >> 2;

    const int row0 = blockIdx.y * 128;
    const int col0 = blockIdx.x * 128;

    const float* Aptr = A + (size_t)row0 * K;
    const float* Wptr = W + (size_t)col0 * K;

    const int r0_ = tid >> 2;
    const int r1_ = r0_ + 64;
    const int tq  = tid & 3;
    const int c4_ = tq << 2;
    const int p0_ = tq << 1;

    float acc[4][4][4];
#pragma unroll
    for (int mt = 0; mt < 4; mt++)
#pragma unroll
        for (int nt = 0; nt < 4; nt++)
#pragma unroll
            for (int e = 0; e < 4; e++) acc[mt][nt][e] = 0.0f;

    const int nstages = K >> 4;

    float4 pa0 = *(const float4*)(Aptr + (size_t)r0_ * K + c4_);
    float4 pa1 = *(const float4*)(Aptr + (size_t)r1_ * K + c4_);
    float4 pb0 = *(const float4*)(Wptr + (size_t)r0_ * K + c4_);
    float4 pb1 = *(const float4*)(Wptr + (size_t)r1_ * K + c4_);
    stage_split(sA[0][0], sA[0][1], p0_, r0_, pa0);
    stage_split(sA[0][0], sA[0][1], p0_, r1_, pa1);
    stage_split(sB[0][0], sB[0][1], p0_, r0_, pb0);
    stage_split(sB[0][0], sB[0][1], p0_, r1_, pb1);
    __syncthreads();

    const int pA = lq;
    const int pB = lq + 4;

    for (int i = 0; i < nstages; i++) {
        const int cur = i & 1;
        const bool more = (i + 1 < nstages);

        if (more) {
            const size_t koff = (size_t)(i + 1) << 4;
            pa0 = *(const float4*)(Aptr + (size_t)r0_ * K + koff + c4_);
            pa1 = *(const float4*)(Aptr + (size_t)r1_ * K + koff + c4_);
            pb0 = *(const float4*)(Wptr + (size_t)r0_ * K + koff + c4_);
            pb1 = *(const float4*)(Wptr + (size_t)r1_ * K + koff + c4_);
        }

        const uint32_t* Ah = sA[cur][0];
        const uint32_t* Al = sA[cur][1];
        const uint32_t* Bh = sB[cur][0];
        const uint32_t* Bl = sB[cur][1];

        uint32_t bh[4][2], bl[4][2];
#pragma unroll
        for (int nt = 0; nt < 4; nt++) {
            int n = wn * 32 + nt * 8 + lr;
            bh[nt][0] = Bh[SWIZ(pA, n)];
            bh[nt][1] = Bh[SWIZ(pB, n)];
            bl[nt][0] = Bl[SWIZ(pA, n)];
            bl[nt][1] = Bl[SWIZ(pB, n)];
        }

#pragma unroll
        for (int mt = 0; mt < 4; mt++) {
            int r = wm * 64 + mt * 16 + lr;
            uint32_t ah[4], al[4];
            ah[0] = Ah[SWIZ(pA, r)];
            ah[1] = Ah[SWIZ(pA, r + 8)];
            ah[2] = Ah[SWIZ(pB, r)];
            ah[3] = Ah[SWIZ(pB, r + 8)];
            al[0] = Al[SWIZ(pA, r)];
            al[1] = Al[SWIZ(pA, r + 8)];
            al[2] = Al[SWIZ(pB, r)];
            al[3] = Al[SWIZ(pB, r + 8)];
#pragma unroll
            for (int nt = 0; nt < 4; nt++) {
                MMA_BF16(acc[mt][nt], ah, bl[nt]);
                MMA_BF16(acc[mt][nt], al, bh[nt]);
                MMA_BF16(acc[mt][nt], ah, bh[nt]);
            }
        }

        if (more) {
            const int nxt = cur ^ 1;
            stage_split(sA[nxt][0], sA[nxt][1], p0_, r0_, pa0);
            stage_split(sA[nxt][0], sA[nxt][1], p0_, r1_, pa1);
            stage_split(sB[nxt][0], sB[nxt][1], p0_, r0_, pb0);
            stage_split(sB[nxt][0], sB[nxt][1], p0_, r1_, pb1);
        }
        __syncthreads();
    }

#pragma unroll
    for (int nt = 0; nt < 4; nt++) {
        int c  = col0 + wn * 32 + nt * 8 + 2 * lq;
        float bv0 = bias[c];
        float bv1 = bias[c + 1];
#pragma unroll
        for (int mt = 0; mt < 4; mt++) {
            int r = row0 + wm * 64 + mt * 16 + lr;
            float2 o0, o1;
            o0.x = acc[mt][nt][0] + bv0;
            o0.y = acc[mt][nt][1] + bv1;
            o1.x = acc[mt][nt][2] + bv0;
            o1.y = acc[mt][nt][3] + bv1;
            if (RELU) {
                o0.x = fmaxf(o0.x, 0.0f); o0.y = fmaxf(o0.y, 0.0f);
                o1.x = fmaxf(o1.x, 0.0f); o1.y = fmaxf(o1.y, 0.0f);
            }
            *(float2*)&C[(size_t)r * N + c]       = o0;
            *(float2*)&C[(size_t)(r + 8) * N + c] = o1;
        }
    }
}

// ---------------------------------------------------------------------------
// Tensor-core flash attention (split-bf16 x3 on BOTH QK^T and PV).
// Block: 256 thr / 8 warps, 128-query tile per (b,h). Warp w owns rows
// q0+16w..+15 and ALL 64 keys of each key tile -> warp-local softmax.
// smem: K,V hi/lo planes [32 kpairs][64 rows] u32, swizzle p*64+(r^((p&3)<<3)).
// Q kept in registers (a-frags). P->A via the FA2 C-to-A fragment identity.
// scores = (kq.kq)*0.125*fr[row], strict mask col>=row on diagonal tiles,
// ctx row 0 zeroed at write.
// ---------------------------------------------------------------------------
#define SWZ64(p, r) (((p) << 6) + ((r) ^ (((p) & 3) << 3)))

__global__ void __launch_bounds__(256)
attn_tc_kernel(const float* __restrict__ kq,
               const float* __restrict__ v,
               const float* __restrict__ fr,
               float* __restrict__ ctx)
{
    __shared__ uint32_t sKh[32 * 64], sKl[32 * 64];
    __shared__ uint32_t sVh[32 * 64], sVl[32 * 64];

    const int qt   = blockIdx.x;          // 0..3 (128-row tiles)
    const int h    = blockIdx.y;
    const int b    = blockIdx.z;
    const int q0   = qt * 128;
    const int tid  = threadIdx.x;
    const int warp = tid >> 5;
    const int lane = tid & 31;
    const int lr   = lane >> 2;
    const int lq   = lane & 3;

    const int r0g = q0 + warp * 16 + lr;          // seq row (this lane, c0/c1)
    const size_t hb = (size_t)(b * S_) * D_ + h * DK_;

    // ---- Q fragments (hi/lo), loaded once ----
    uint32_t qh[4][4], ql[4][4];
#pragma unroll
    for (int ks = 0; ks < 4; ks++) {
#pragma unroll
        for (int half = 0; half < 2; half++) {
            int dk = ks * 16 + half * 8 + 2 * lq;
            float2 v0 = *(const float2*)&kq[hb + (size_t)r0g * D_ + dk];
            float2 v1 = *(const float2*)&kq[hb + (size_t)(r0g + 8) * D_ + dk];
            uint32_t th, tl;
            split2(v0.x, v0.y, th, tl);
            qh[ks][half * 2 + 0] = th; ql[ks][half * 2 + 0] = tl;
            split2(v1.x, v1.y, th, tl);
            qh[ks][half * 2 + 1] = th; ql[ks][half * 2 + 1] = tl;
        }
    }
    // a-frag convention: a0=(r0,kb0) a1=(r1,kb0) a2=(r0,kb1) a3=(r1,kb1) — matches.

    float m0 = -1e30f, m1 = -1e30f, l0 = 0.0f, l1 = 0.0f;
    float acc[8][4];
#pragma unroll
    for (int nt = 0; nt < 8; nt++)
#pragma unroll
        for (int e = 0; e < 4; e++) acc[nt][e] = 0.0f;

    const float rf0 = 0.125f * fr[b * S_ + r0g];
    const float rf1 = 0.125f * fr[b * S_ + r0g + 8];

    const int nkt = 2 * qt + 2;
    for (int kt = 0; kt < nkt; kt++) {
        const int t0 = kt * 64;
        __syncthreads();

        // ---- stage K tile: [kpair=dk/2][key], pairs along dk ----
        for (int t = tid; t < 1024; t += 256) {
            int key = t >> 4;
            int c4  = (t & 15) << 2;
            float4 kv = *(const float4*)&kq[hb + (size_t)(t0 + key) * D_ + c4];
            uint32_t h01, l01, h23, l23;
            split2(kv.x, kv.y, h01, l01);
            split2(kv.z, kv.w, h23, l23);
            int p = c4 >> 1;
            sKh[SWZ64(p, key)]     = h01;
            sKl[SWZ64(p, key)]     = l01;
            sKh[SWZ64(p + 1, key)] = h23;
            sKl[SWZ64(p + 1, key)] = l23;
        }
        // ---- stage V tile: [kpair=key/2][dk], pairs across keys ----
        for (int t = tid; t < 512; t += 256) {
            int kp = t >> 4;
            int c4 = (t & 15) << 2;
            const float* vb0 = &v[hb + (size_t)(t0 + 2 * kp) * D_ + c4];
            float4 a0 = *(const float4*)vb0;
            float4 a1 = *(const float4*)(vb0 + D_);
            uint32_t th, tl;
            split2(a0.x, a1.x, th, tl);
            sVh[SWZ64(kp, c4 + 0)] = th; sVl[SWZ64(kp, c4 + 0)] = tl;
            split2(a0.y, a1.y, th, tl);
            sVh[SWZ64(kp, c4 + 1)] = th; sVl[SWZ64(kp, c4 + 1)] = tl;
            split2(a0.z, a1.z, th, tl);
            sVh[SWZ64(kp, c4 + 2)] = th; sVl[SWZ64(kp, c4 + 2)] = tl;
            split2(a0.w, a1.w, th, tl);
            sVh[SWZ64(kp, c4 + 3)] = th; sVl[SWZ64(kp, c4 + 3)] = tl;
        }
        __syncthreads();

        // ---- S = Q K^T ----
        float sc[8][4];
#pragma unroll
        for (int nt = 0; nt < 8; nt++)
#pragma unroll
            for (int e = 0; e < 4; e++) sc[nt][e] = 0.0f;

#pragma unroll
        for (int ks = 0; ks < 4; ks++) {
            int pa = ks * 8 + lq, pb = pa + 4;
#pragma unroll
            for (int nt = 0; nt < 8; nt++) {
                int n = nt * 8 + lr;
                uint32_t bh[2] = { sKh[SWZ64(pa, n)], sKh[SWZ64(pb, n)] };
                uint32_t bl[2] = { sKl[SWZ64(pa, n)], sKl[SWZ64(pb, n)] };
                MMA_BF16(sc[nt], qh[ks], bl);
                MMA_BF16(sc[nt], ql[ks], bh);
                MMA_BF16(sc[nt], qh[ks], bh);
            }
        }

        // ---- scale * fr, strict causal mask on diagonal tiles ----
        const bool needmask = (t0 + 63 >= q0 + warp * 16);
#pragma unroll
        for (int nt = 0; nt < 8; nt++) {
            sc[nt][0] *= rf0; sc[nt][1] *= rf0;
            sc[nt][2] *= rf1; sc[nt][3] *= rf1;
            if (needmask) {
                int c0 = t0 + nt * 8 + 2 * lq;
                if (c0     >= r0g)     sc[nt][0] = -1e30f;
                if (c0 + 1 >= r0g)     sc[nt][1] = -1e30f;
                if (c0     >= r0g + 8) sc[nt][2] = -1e30f;
                if (c0 + 1 >= r0g + 8) sc[nt][3] = -1e30f;
            }
        }

        // ---- online softmax (warp-local: quad shfl over lq) ----
        float mt0 = -1e30f, mt1 = -1e30f;
#pragma unroll
        for (int nt = 0; nt < 8; nt++) {
            mt0 = fmaxf(mt0, fmaxf(sc[nt][0], sc[nt][1]));
            mt1 = fmaxf(mt1, fmaxf(sc[nt][2], sc[nt][3]));
        }
        mt0 = fmaxf(mt0, __shfl_xor_sync(0xffffffffu, mt0, 1));
        mt0 = fmaxf(mt0, __shfl_xor_sync(0xffffffffu, mt0, 2));
        mt1 = fmaxf(mt1, __shfl_xor_sync(0xffffffffu, mt1, 1));
        mt1 = fmaxf(mt1, __shfl_xor_sync(0xffffffffu, mt1, 2));

        float mn0 = fmaxf(m0, mt0), mn1 = fmaxf(m1, mt1);
        float al0 = __expf(m0 - mn0), al1 = __expf(m1 - mn1);
        m0 = mn0; m1 = mn1;

        float rs0 = 0.0f, rs1 = 0.0f;
#pragma unroll
        for (int nt = 0; nt < 8; nt++) {
            sc[nt][0] = __expf(sc[nt][0] - mn0);
            sc[nt][1] = __expf(sc[nt][1] - mn0);
            sc[nt][2] = __expf(sc[nt][2] - mn1);
            sc[nt][3] = __expf(sc[nt][3] - mn1);
            rs0 += sc[nt][0] + sc[nt][1];
            rs1 += sc[nt][2] + sc[nt][3];
        }
        rs0 += __shfl_xor_sync(0xffffffffu, rs0, 1);
        rs0 += __shfl_xor_sync(0xffffffffu, rs0, 2);
        rs1 += __shfl_xor_sync(0xffffffffu, rs1, 1);
        rs1 += __shfl_xor_sync(0xffffffffu, rs1, 2);
        l0 = l0 * al0 + rs0;
        l1 = l1 * al1 + rs1;

#pragma unroll
        for (int nt = 0; nt < 8; nt++) {
            acc[nt][0] *= al0; acc[nt][1] *= al0;
            acc[nt][2] *= al1; acc[nt][3] *= al1;
        }

        // ---- O += P V (P from sc via C->A fragment identity, split hi/lo) ----
#pragma unroll
        for (int ks = 0; ks < 4; ks++) {
            uint32_t ph[4], pl[4];
            split2(sc[2 * ks][0],     sc[2 * ks][1],     ph[0], pl[0]);
            split2(sc[2 * ks][2],     sc[2 * ks][3],     ph[1], pl[1]);
            split2(sc[2 * ks + 1][0], sc[2 * ks + 1][1], ph[2], pl[2]);
            split2(sc[2 * ks + 1][2], sc[2 * ks + 1][3], ph[3], pl[3]);
            int pa = ks * 8 + lq, pb = pa + 4;
#pragma unroll
            for (int nt = 0; nt < 8; nt++) {
                int n = nt * 8 + lr;
                uint32_t vh[2] = { sVh[SWZ64(pa, n)], sVh[SWZ64(pb, n)] };
                uint32_t vl[2] = { sVl[SWZ64(pa, n)], sVl[SWZ64(pb, n)] };
                MMA_BF16(acc[nt], ph, vl);
                MMA_BF16(acc[nt], pl, vh);
                MMA_BF16(acc[nt], ph, vh);
            }
        }
    }

    // ---- write ctx (row 0 forced to zero) ----
    const float inv0 = 1.0f / l0;
    const float inv1 = 1.0f / l1;
#pragma unroll
    for (int nt = 0; nt < 8; nt++) {
        int c = nt * 8 + 2 * lq;
        float2 o0, o1;
        o0.x = acc[nt][0] * inv0; o0.y = acc[nt][1] * inv0;
        o1.x = acc[nt][2] * inv1; o1.y = acc[nt][3] * inv1;
        if (r0g == 0) { o0.x = 0.0f; o0.y = 0.0f; }
        *(float2*)&ctx[hb + (size_t)r0g * D_ + c]       = o0;
        *(float2*)&ctx[hb + (size_t)(r0g + 8) * D_ + c] = o1;
    }
}

// ---------------------------------------------------------------------------
// xout = LayerNorm(xin + res) * g + beta
// ---------------------------------------------------------------------------
__global__ void __launch_bounds__(128)
add_ln_kernel(const float* __restrict__ xin,
              const float* __restrict__ res,
              const float* __restrict__ g,
              const float* __restrict__ beta,
              float* __restrict__ xout)
{
    const int row = blockIdx.x;
    const int tid = threadIdx.x;

    float4 a = ((const float4*)(xin + (size_t)row * D_))[tid];
    float4 b = ((const float4*)(res + (size_t)row * D_))[tid];
    float v0 = a.x + b.x, v1 = a.y + b.y, v2 = a.z + b.z, v3 = a.w + b.w;

    float s  = v0 + v1 + v2 + v3;
    float sq = v0 * v0 + v1 * v1 + v2 * v2 + v3 * v3;
#pragma unroll
    for (int off = 16; off >= 1; off >>= 1) {
        s  += __shfl_xor_sync(0xffffffffu, s,  off);
        sq += __shfl_xor_sync(0xffffffffu, sq, off);
    }
    __shared__ float ss[4], ssq[4];
    int w = tid >> 5, lane = tid & 31;
    if (lane == 0) { ss[w] = s; ssq[w] = sq; }
    __syncthreads();
    s  = ss[0]  + ss[1]  + ss[2]  + ss[3];
    sq = ssq[0] + ssq[1] + ssq[2] + ssq[3];

    const float mu   = s * (1.0f / (float)D_);
    const float var  = sq * (1.0f / (float)D_) - mu * mu;
    const float rstd = rsqrtf(var + 1e-5f);

    float4 gg = ((const float4*)g)[tid];
    float4 bb = ((const float4*)beta)[tid];
    float4 o;
    o.x = (v0 - mu) * rstd * gg.x + bb.x;
    o.y = (v1 - mu) * rstd * gg.y + bb.y;
    o.z = (v2 - mu) * rstd * gg.z + bb.z;
    o.w = (v3 - mu) * rstd * gg.w + bb.w;
    ((float4*)(xout + (size_t)row * D_))[tid] = o;
}

// ---------------------------------------------------------------------------
// Orchestration
// ---------------------------------------------------------------------------
extern "C" void kernel_launch(void* const* d_in, const int* in_sizes, int n_in,
                              void* d_out, int out_size)
{
    const float* q   = (const float*)d_in[0];
    const float* qa  = (const float*)d_in[1];
    const float* fr  = (const float*)d_in[2];
    const float* pe  = (const float*)d_in[3];
    const float* Wk  = (const float*)d_in[4];
    const float* bk  = (const float*)d_in[5];
    const float* Wv  = (const float*)d_in[6];
    const float* bv  = (const float*)d_in[7];
    const float* Wo  = (const float*)d_in[8];
    const float* bo  = (const float*)d_in[9];
    const float* W1  = (const float*)d_in[10];
    const float* b1  = (const float*)d_in[11];
    const float* W2  = (const float*)d_in[12];
    const float* b2  = (const float*)d_in[13];
    const float* g1  = (const float*)d_in[14];
    const float* be1 = (const float*)d_in[15];
    const float* g2  = (const float*)d_in[16];
    const float* be2 = (const float*)d_in[17];
    float* out = (float*)d_out;

    float *x, *y, *kqb, *vb, *ctxb, *ob, *hb;
    cudaGetSymbolAddress((void**)&x,    g_x);
    cudaGetSymbolAddress((void**)&y,    g_y);
    cudaGetSymbolAddress((void**)&kqb,  g_kq);
    cudaGetSymbolAddress((void**)&vb,   g_v);
    cudaGetSymbolAddress((void**)&ctxb, g_ctx);
    cudaGetSymbolAddress((void**)&ob,   g_o);
    cudaGetSymbolAddress((void**)&hb,   g_h);

    {
        int n4 = MROWS * D_ / 4;
        add_pos_kernel<<<(n4 + 255) / 256, 256>>>(
            (const float4*)q, (const float4*)qa, (const float4*)pe,
            (float4*)x, (float4*)y);
    }

    const dim3 gD(D_ / 128, MROWS / 128);   // (4, 128)
    const dim3 gF(F_ / 128, MROWS / 128);   // (16, 128)
    const dim3 gA(S_ / 128, H_, B_);        // (4, 8, 32)

    for (int l = 0; l < L_; l++) {
        const size_t wDD = (size_t)l * D_ * D_;
        const size_t wFD = (size_t)l * F_ * D_;

        gemm_tc_kernel<false><<<gD, 256>>>(x, Wk + wDD, bk + l * D_, kqb, MROWS, D_, D_);
        gemm_tc_kernel<false><<<gD, 256>>>(y, Wv + wDD, bv + l * D_, vb,  MROWS, D_, D_);
        attn_tc_kernel<<<gA, 256>>>(kqb, vb, fr, ctxb);
        gemm_tc_kernel<false><<<gD, 256>>>(ctxb, Wo + wDD, bo + l * D_, ob, MROWS, D_, D_);
        add_ln_kernel<<<MROWS, 128>>>(x, ob, g1 + l * D_, be1 + l * D_, x);
        gemm_tc_kernel<true ><<<gF, 256>>>(x, W1 + wFD, b1 + l * F_, hb, MROWS, F_, D_);
        gemm_tc_kernel<false><<<gD, 256>>>(hb, W2 + wFD, b2 + l * D_, ob, MROWS, D_, F_);
        add_ln_kernel<<<MROWS, 128>>>(x, ob, g2 + l * D_, be2 + l * D_,
                                      (l == L_ - 1) ? out : x);
    }
}